// round 3
// baseline (speedup 1.0000x reference)
#include <cuda_runtime.h>
#include <math.h>

#define NN 500000
#define NE 8000000

// Scratch (device globals — no allocation in kernel_launch)
__device__ float g_deg[NN];
__device__ float g_dinv[NN];
__device__ float g_p[NN];            // x*dinv
__device__ float g_a1[NN];           // scatter accumulator layer 1
__device__ float2 g_q[NN];           // z*dinv per node (2 floats)
__device__ float2 g_a2[NN];          // scatter accumulator layer 2

// ---------------- init: deg=1 (self loop), a1=0, a2=0 ----------------
__global__ void __launch_bounds__(256) k_init(int n) {
    int i = blockIdx.x * blockDim.x + threadIdx.x;
    if (i < n) {
        g_deg[i] = 1.0f;
        g_a1[i] = 0.0f;
        g_a2[i] = make_float2(0.0f, 0.0f);
    }
}

// ---------------- count in-degree over dst (8 edges/thread) ----------------
__global__ void __launch_bounds__(256) k_count(const int* __restrict__ dst, int ne) {
    int i = blockIdx.x * blockDim.x + threadIdx.x;
    int e = i * 8;
    if (e + 8 <= ne) {
        int4 d0 = *reinterpret_cast<const int4*>(dst + e);
        int4 d1 = *reinterpret_cast<const int4*>(dst + e + 4);
        atomicAdd(&g_deg[d0.x], 1.0f);
        atomicAdd(&g_deg[d0.y], 1.0f);
        atomicAdd(&g_deg[d0.z], 1.0f);
        atomicAdd(&g_deg[d0.w], 1.0f);
        atomicAdd(&g_deg[d1.x], 1.0f);
        atomicAdd(&g_deg[d1.y], 1.0f);
        atomicAdd(&g_deg[d1.z], 1.0f);
        atomicAdd(&g_deg[d1.w], 1.0f);
    } else {
        for (; e < ne; e++) atomicAdd(&g_deg[dst[e]], 1.0f);
    }
}

// ---------------- dinv = rsqrt(deg); p = x * dinv ----------------
__global__ void __launch_bounds__(256) k_prep(const float* __restrict__ x, int n) {
    int i = blockIdx.x * blockDim.x + threadIdx.x;
    if (i < n) {
        float dv = rsqrtf(g_deg[i]);
        g_dinv[i] = dv;
        g_p[i] = x[i] * dv;
    }
}

// ---------------- layer-1 scalar scatter: a1[dst] += p[src] (8 edges/thread) --
__global__ void __launch_bounds__(256) k_scatter1(const int* __restrict__ src,
                                                  const int* __restrict__ dst, int ne) {
    int i = blockIdx.x * blockDim.x + threadIdx.x;
    int e = i * 8;
    if (e + 8 <= ne) {
        int4 s0 = *reinterpret_cast<const int4*>(src + e);
        int4 s1 = *reinterpret_cast<const int4*>(src + e + 4);
        int4 d0 = *reinterpret_cast<const int4*>(dst + e);
        int4 d1 = *reinterpret_cast<const int4*>(dst + e + 4);
        // front-batch all 8 gathers (maximize MLP)
        float p0 = __ldg(&g_p[s0.x]);
        float p1 = __ldg(&g_p[s0.y]);
        float p2 = __ldg(&g_p[s0.z]);
        float p3 = __ldg(&g_p[s0.w]);
        float p4 = __ldg(&g_p[s1.x]);
        float p5 = __ldg(&g_p[s1.y]);
        float p6 = __ldg(&g_p[s1.z]);
        float p7 = __ldg(&g_p[s1.w]);
        atomicAdd(&g_a1[d0.x], p0);
        atomicAdd(&g_a1[d0.y], p1);
        atomicAdd(&g_a1[d0.z], p2);
        atomicAdd(&g_a1[d0.w], p3);
        atomicAdd(&g_a1[d1.x], p4);
        atomicAdd(&g_a1[d1.y], p5);
        atomicAdd(&g_a1[d1.z], p6);
        atomicAdd(&g_a1[d1.w], p7);
    } else {
        for (; e < ne; e++) atomicAdd(&g_a1[dst[e]], g_p[src[e]]);
    }
}

// ---------------- per-node MLP: s1 -> relu(s1*W1+b1) @ W2 -> q = z*dinv ----
__global__ void __launch_bounds__(256) k_node(const float* __restrict__ W1,
                                              const float* __restrict__ b1,
                                              const float* __restrict__ W2, int n) {
    __shared__ float sW1[16], sb1[16], sW2[32];
    int t = threadIdx.x;
    if (t < 16) { sW1[t] = W1[t]; sb1[t] = b1[t]; }
    if (t < 32) { sW2[t] = W2[t]; }
    __syncthreads();
    int i = blockIdx.x * blockDim.x + t;
    if (i < n) {
        float dv = g_dinv[i];
        float s1 = dv * (g_a1[i] + g_p[i]);
        float z0 = 0.0f, z1 = 0.0f;
        #pragma unroll
        for (int k = 0; k < 16; k++) {
            float h = fmaxf(fmaf(s1, sW1[k], sb1[k]), 0.0f);
            z0 = fmaf(h, sW2[2 * k + 0], z0);
            z1 = fmaf(h, sW2[2 * k + 1], z1);
        }
        g_q[i] = make_float2(z0 * dv, z1 * dv);
    }
}

// ---------------- layer-2 vector scatter: a2[dst] += q[src] (8 edges/thread) --
__global__ void __launch_bounds__(256) k_scatter2(const int* __restrict__ src,
                                                  const int* __restrict__ dst, int ne) {
    int i = blockIdx.x * blockDim.x + threadIdx.x;
    int e = i * 8;
    if (e + 8 <= ne) {
        int4 s0 = *reinterpret_cast<const int4*>(src + e);
        int4 s1 = *reinterpret_cast<const int4*>(src + e + 4);
        int4 d0 = *reinterpret_cast<const int4*>(dst + e);
        int4 d1 = *reinterpret_cast<const int4*>(dst + e + 4);
        float2 q0 = __ldg(&g_q[s0.x]);
        float2 q1 = __ldg(&g_q[s0.y]);
        float2 q2 = __ldg(&g_q[s0.z]);
        float2 q3 = __ldg(&g_q[s0.w]);
        float2 q4 = __ldg(&g_q[s1.x]);
        float2 q5 = __ldg(&g_q[s1.y]);
        float2 q6 = __ldg(&g_q[s1.z]);
        float2 q7 = __ldg(&g_q[s1.w]);
        atomicAdd(&g_a2[d0.x], q0);
        atomicAdd(&g_a2[d0.y], q1);
        atomicAdd(&g_a2[d0.z], q2);
        atomicAdd(&g_a2[d0.w], q3);
        atomicAdd(&g_a2[d1.x], q4);
        atomicAdd(&g_a2[d1.y], q5);
        atomicAdd(&g_a2[d1.z], q6);
        atomicAdd(&g_a2[d1.w], q7);
    } else {
        for (; e < ne; e++) {
            atomicAdd(&g_a2[dst[e]], g_q[src[e]]);
        }
    }
}

// ---------------- finalize: out = log_softmax(dinv*(a2+q) + b2) ----------------
__global__ void __launch_bounds__(256) k_final(const float* __restrict__ b2,
                                               float* __restrict__ out, int n) {
    int i = blockIdx.x * blockDim.x + threadIdx.x;
    if (i < n) {
        float dv = g_dinv[i];
        float2 q = g_q[i];
        float2 a = g_a2[i];
        float v0 = fmaf(dv, a.x + q.x, __ldg(&b2[0]));
        float v1 = fmaf(dv, a.y + q.y, __ldg(&b2[1]));
        float m = fmaxf(v0, v1);
        float lse = m + logf(expf(v0 - m) + expf(v1 - m));
        *reinterpret_cast<float2*>(out + 2 * i) = make_float2(v0 - lse, v1 - lse);
    }
}

extern "C" void kernel_launch(void* const* d_in, const int* in_sizes, int n_in,
                              void* d_out, int out_size) {
    const float* x  = (const float*)d_in[0];
    const int*   ei = (const int*)d_in[1];
    const float* W1 = (const float*)d_in[2];
    const float* b1 = (const float*)d_in[3];
    const float* W2 = (const float*)d_in[4];
    const float* b2 = (const float*)d_in[5];
    float* out = (float*)d_out;

    int n  = in_sizes[0];          // N nodes (x is [N,1])
    int ne = in_sizes[1] / 2;      // edge_index is [2, E]
    const int* src = ei;
    const int* dst = ei + ne;

    const int T = 256;
    int gridN  = (n + T - 1) / T;
    int gridE8 = ((ne + 7) / 8 + T - 1) / T;

    k_init<<<gridN, T>>>(n);
    k_count<<<gridE8, T>>>(dst, ne);
    k_prep<<<gridN, T>>>(x, n);
    k_scatter1<<<gridE8, T>>>(src, dst, ne);
    k_node<<<gridN, T>>>(W1, b1, W2, n);
    k_scatter2<<<gridE8, T>>>(src, dst, ne);
    k_final<<<gridN, T>>>(b2, out, n);
}

// round 4
// speedup vs baseline: 1.0339x; 1.0339x over previous
#include <cuda_runtime.h>
#include <math.h>

#define NN 500000
#define NE 8000000

// Scratch (device globals — no allocation in kernel_launch)
__device__ float g_deg[NN];          // zeroed via memset; self-loop added in prep
__device__ float g_dinv[NN];
__device__ float g_p[NN];            // x*dinv
__device__ float g_a1[NN];           // scatter accumulator layer 1 (zeroed)
__device__ float2 g_q[NN];           // z*dinv per node (2 floats)
__device__ float2 g_a2[NN];          // scatter accumulator layer 2 (zeroed)

// ---------------- count in-degree over dst (4 edges/thread) ----------------
__global__ void __launch_bounds__(256) k_count(const int* __restrict__ dst, int ne) {
    int i = blockIdx.x * blockDim.x + threadIdx.x;
    int e = i * 4;
    if (e + 4 <= ne) {
        int4 d = *reinterpret_cast<const int4*>(dst + e);
        atomicAdd(&g_deg[d.x], 1.0f);
        atomicAdd(&g_deg[d.y], 1.0f);
        atomicAdd(&g_deg[d.z], 1.0f);
        atomicAdd(&g_deg[d.w], 1.0f);
    } else {
        for (; e < ne; e++) atomicAdd(&g_deg[dst[e]], 1.0f);
    }
}

// ---------------- dinv = rsqrt(deg+1); p = x * dinv (4 nodes/thread) -------
__global__ void __launch_bounds__(256) k_prep(const float* __restrict__ x, int n) {
    int i = blockIdx.x * blockDim.x + threadIdx.x;
    int j = i * 4;
    if (j + 4 <= n) {
        float4 dg = *reinterpret_cast<const float4*>(g_deg + j);
        float4 xv = *reinterpret_cast<const float4*>(x + j);
        float4 dv;
        dv.x = rsqrtf(dg.x + 1.0f);
        dv.y = rsqrtf(dg.y + 1.0f);
        dv.z = rsqrtf(dg.z + 1.0f);
        dv.w = rsqrtf(dg.w + 1.0f);
        *reinterpret_cast<float4*>(g_dinv + j) = dv;
        float4 pv = make_float4(xv.x * dv.x, xv.y * dv.y, xv.z * dv.z, xv.w * dv.w);
        *reinterpret_cast<float4*>(g_p + j) = pv;
    } else {
        for (; j < n; j++) {
            float dv = rsqrtf(g_deg[j] + 1.0f);
            g_dinv[j] = dv;
            g_p[j] = x[j] * dv;
        }
    }
}

// ---------------- layer-1 scalar scatter: a1[dst] += p[src] (4 edges/thread) --
__global__ void __launch_bounds__(256) k_scatter1(const int* __restrict__ src,
                                                  const int* __restrict__ dst, int ne) {
    int i = blockIdx.x * blockDim.x + threadIdx.x;
    int e = i * 4;
    if (e + 4 <= ne) {
        int4 s = *reinterpret_cast<const int4*>(src + e);
        int4 d = *reinterpret_cast<const int4*>(dst + e);
        float p0 = g_p[s.x], p1 = g_p[s.y], p2 = g_p[s.z], p3 = g_p[s.w];
        atomicAdd(&g_a1[d.x], p0);
        atomicAdd(&g_a1[d.y], p1);
        atomicAdd(&g_a1[d.z], p2);
        atomicAdd(&g_a1[d.w], p3);
    } else {
        for (; e < ne; e++) atomicAdd(&g_a1[dst[e]], g_p[src[e]]);
    }
}

// ---------------- per-node MLP: s1 -> relu(s1*W1+b1) @ W2 -> q = z*dinv ----
__global__ void __launch_bounds__(256) k_node(const float* __restrict__ W1,
                                              const float* __restrict__ b1,
                                              const float* __restrict__ W2, int n) {
    __shared__ float sW1[16], sb1[16], sW2[32];
    int t = threadIdx.x;
    if (t < 16) { sW1[t] = W1[t]; sb1[t] = b1[t]; }
    if (t < 32) { sW2[t] = W2[t]; }
    __syncthreads();
    int i = blockIdx.x * blockDim.x + t;
    if (i < n) {
        float dv = g_dinv[i];
        float s1 = dv * (g_a1[i] + g_p[i]);
        float z0 = 0.0f, z1 = 0.0f;
        #pragma unroll
        for (int k = 0; k < 16; k++) {
            float h = fmaxf(fmaf(s1, sW1[k], sb1[k]), 0.0f);
            z0 = fmaf(h, sW2[2 * k + 0], z0);
            z1 = fmaf(h, sW2[2 * k + 1], z1);
        }
        g_q[i] = make_float2(z0 * dv, z1 * dv);
    }
}

// ---------------- layer-2 vector scatter: a2[dst] += q[src] (float2 RED) ----
__global__ void __launch_bounds__(256) k_scatter2(const int* __restrict__ src,
                                                  const int* __restrict__ dst, int ne) {
    int i = blockIdx.x * blockDim.x + threadIdx.x;
    int e = i * 4;
    if (e + 4 <= ne) {
        int4 s = *reinterpret_cast<const int4*>(src + e);
        int4 d = *reinterpret_cast<const int4*>(dst + e);
        float2 q0 = g_q[s.x];
        float2 q1 = g_q[s.y];
        float2 q2 = g_q[s.z];
        float2 q3 = g_q[s.w];
        atomicAdd(&g_a2[d.x], q0);
        atomicAdd(&g_a2[d.y], q1);
        atomicAdd(&g_a2[d.z], q2);
        atomicAdd(&g_a2[d.w], q3);
    } else {
        for (; e < ne; e++) {
            atomicAdd(&g_a2[dst[e]], g_q[src[e]]);
        }
    }
}

// ---------------- finalize: out = log_softmax(dinv*(a2+q) + b2), 2 nodes/thread ----
__global__ void __launch_bounds__(256) k_final(const float* __restrict__ b2,
                                               float* __restrict__ out, int n) {
    int i = blockIdx.x * blockDim.x + threadIdx.x;
    int j = i * 2;
    float bb0 = __ldg(&b2[0]), bb1 = __ldg(&b2[1]);
    if (j + 2 <= n) {
        float2 dv2 = *reinterpret_cast<const float2*>(g_dinv + j);
        float4 q = *reinterpret_cast<const float4*>(reinterpret_cast<const float*>(g_q) + 2 * j);
        float4 a = *reinterpret_cast<const float4*>(reinterpret_cast<const float*>(g_a2) + 2 * j);
        float v0 = fmaf(dv2.x, a.x + q.x, bb0);
        float v1 = fmaf(dv2.x, a.y + q.y, bb1);
        float m0 = fmaxf(v0, v1);
        float l0 = m0 + logf(expf(v0 - m0) + expf(v1 - m0));
        float v2 = fmaf(dv2.y, a.z + q.z, bb0);
        float v3 = fmaf(dv2.y, a.w + q.w, bb1);
        float m1 = fmaxf(v2, v3);
        float l1 = m1 + logf(expf(v2 - m1) + expf(v3 - m1));
        *reinterpret_cast<float4*>(out + 2 * j) =
            make_float4(v0 - l0, v1 - l0, v2 - l1, v3 - l1);
    } else if (j < n) {
        float dv = g_dinv[j];
        float2 q = g_q[j];
        float2 a = g_a2[j];
        float v0 = fmaf(dv, a.x + q.x, bb0);
        float v1 = fmaf(dv, a.y + q.y, bb1);
        float m = fmaxf(v0, v1);
        float lse = m + logf(expf(v0 - m) + expf(v1 - m));
        out[2 * j + 0] = v0 - lse;
        out[2 * j + 1] = v1 - lse;
    }
}

extern "C" void kernel_launch(void* const* d_in, const int* in_sizes, int n_in,
                              void* d_out, int out_size) {
    const float* x  = (const float*)d_in[0];
    const int*   ei = (const int*)d_in[1];
    const float* W1 = (const float*)d_in[2];
    const float* b1 = (const float*)d_in[3];
    const float* W2 = (const float*)d_in[4];
    const float* b2 = (const float*)d_in[5];
    float* out = (float*)d_out;

    int n  = in_sizes[0];          // N nodes (x is [N,1])
    int ne = in_sizes[1] / 2;      // edge_index is [2, E]
    const int* src = ei;
    const int* dst = ei + ne;

    // zero scratch via memset nodes (graph-capturable, no kernel launch)
    void* p_deg = nullptr; void* p_a1 = nullptr; void* p_a2 = nullptr;
    cudaGetSymbolAddress(&p_deg, g_deg);
    cudaGetSymbolAddress(&p_a1, g_a1);
    cudaGetSymbolAddress(&p_a2, g_a2);
    cudaMemsetAsync(p_deg, 0, (size_t)n * sizeof(float));
    cudaMemsetAsync(p_a1, 0, (size_t)n * sizeof(float));
    cudaMemsetAsync(p_a2, 0, (size_t)n * sizeof(float2));

    const int T = 256;
    int gridN   = (n + T - 1) / T;
    int gridN4  = ((n + 3) / 4 + T - 1) / T;
    int gridN2t = ((n + 1) / 2 + T - 1) / T;
    int gridE4  = ((ne + 3) / 4 + T - 1) / T;

    k_count<<<gridE4, T>>>(dst, ne);
    k_prep<<<gridN4, T>>>(x, n);
    k_scatter1<<<gridE4, T>>>(src, dst, ne);
    k_node<<<gridN, T>>>(W1, b1, W2, n);
    k_scatter2<<<gridE4, T>>>(src, dst, ne);
    k_final<<<gridN2t, T>>>(b2, out, n);
}

// round 5
// speedup vs baseline: 1.0356x; 1.0017x over previous
#include <cuda_runtime.h>
#include <math.h>

#define NN 500000
#define NE 8000000

// Scratch (device globals — no allocation in kernel_launch)
__device__ float g_deg[NN];          // zeroed via memset; self-loop added in prep
__device__ float g_dinv[NN];
__device__ float g_p[NN];            // x*dinv
__device__ float g_a1[NN];           // scatter accumulator layer 1 (zeroed)
__device__ float2 g_q[NN];           // z*dinv per node (2 floats)
__device__ float2 g_a2[NN];          // scatter accumulator layer 2 (zeroed)

// ---------------- count in-degree over dst (4 edges/thread) ----------------
__global__ void __launch_bounds__(256) k_count(const int* __restrict__ dst, int ne) {
    int i = blockIdx.x * blockDim.x + threadIdx.x;
    int e = i * 4;
    if (e + 4 <= ne) {
        int4 d = *reinterpret_cast<const int4*>(dst + e);
        atomicAdd(&g_deg[d.x], 1.0f);
        atomicAdd(&g_deg[d.y], 1.0f);
        atomicAdd(&g_deg[d.z], 1.0f);
        atomicAdd(&g_deg[d.w], 1.0f);
    } else {
        for (; e < ne; e++) atomicAdd(&g_deg[dst[e]], 1.0f);
    }
}

// ---------------- dinv = rsqrt(deg+1); p = x * dinv (4 nodes/thread) -------
__global__ void __launch_bounds__(256) k_prep(const float* __restrict__ x, int n) {
    int i = blockIdx.x * blockDim.x + threadIdx.x;
    int j = i * 4;
    if (j + 4 <= n) {
        float4 dg = *reinterpret_cast<const float4*>(g_deg + j);
        float4 xv = *reinterpret_cast<const float4*>(x + j);
        float4 dv;
        dv.x = rsqrtf(dg.x + 1.0f);
        dv.y = rsqrtf(dg.y + 1.0f);
        dv.z = rsqrtf(dg.z + 1.0f);
        dv.w = rsqrtf(dg.w + 1.0f);
        *reinterpret_cast<float4*>(g_dinv + j) = dv;
        float4 pv = make_float4(xv.x * dv.x, xv.y * dv.y, xv.z * dv.z, xv.w * dv.w);
        *reinterpret_cast<float4*>(g_p + j) = pv;
    } else {
        for (; j < n; j++) {
            float dv = rsqrtf(g_deg[j] + 1.0f);
            g_dinv[j] = dv;
            g_p[j] = x[j] * dv;
        }
    }
}

// ---------------- layer-1 scalar scatter: a1[dst] += p[src] (4 edges/thread) --
__global__ void __launch_bounds__(256) k_scatter1(const int* __restrict__ src,
                                                  const int* __restrict__ dst, int ne) {
    int i = blockIdx.x * blockDim.x + threadIdx.x;
    int e = i * 4;
    if (e + 4 <= ne) {
        int4 s = *reinterpret_cast<const int4*>(src + e);
        int4 d = *reinterpret_cast<const int4*>(dst + e);
        // L2-only gathers: bypass L1 tag stage (g_p >> L1 capacity)
        float p0 = __ldcg(&g_p[s.x]);
        float p1 = __ldcg(&g_p[s.y]);
        float p2 = __ldcg(&g_p[s.z]);
        float p3 = __ldcg(&g_p[s.w]);
        atomicAdd(&g_a1[d.x], p0);
        atomicAdd(&g_a1[d.y], p1);
        atomicAdd(&g_a1[d.z], p2);
        atomicAdd(&g_a1[d.w], p3);
    } else {
        for (; e < ne; e++) atomicAdd(&g_a1[dst[e]], __ldcg(&g_p[src[e]]));
    }
}

// ---------------- per-node MLP (2 nodes/thread): q = dinv*(relu(s1*W1+b1)@W2) --
__global__ void __launch_bounds__(256) k_node(const float* __restrict__ W1,
                                              const float* __restrict__ b1,
                                              const float* __restrict__ W2, int n) {
    __shared__ float sW1[16], sb1[16], sW2[32];
    int t = threadIdx.x;
    if (t < 16) { sW1[t] = W1[t]; sb1[t] = b1[t]; }
    if (t < 32) { sW2[t] = W2[t]; }
    __syncthreads();
    int i = blockIdx.x * blockDim.x + t;
    int j = i * 2;
    if (j + 2 <= n) {
        float2 dv = *reinterpret_cast<const float2*>(g_dinv + j);
        float2 a1 = *reinterpret_cast<const float2*>(g_a1 + j);
        float2 pp = *reinterpret_cast<const float2*>(g_p + j);
        float s1a = dv.x * (a1.x + pp.x);
        float s1b = dv.y * (a1.y + pp.y);
        float z0a = 0.0f, z1a = 0.0f, z0b = 0.0f, z1b = 0.0f;
        #pragma unroll
        for (int k = 0; k < 16; k++) {
            float w1 = sW1[k], bb = sb1[k];
            float w20 = sW2[2 * k + 0], w21 = sW2[2 * k + 1];
            float ha = fmaxf(fmaf(s1a, w1, bb), 0.0f);
            float hb = fmaxf(fmaf(s1b, w1, bb), 0.0f);
            z0a = fmaf(ha, w20, z0a);
            z1a = fmaf(ha, w21, z1a);
            z0b = fmaf(hb, w20, z0b);
            z1b = fmaf(hb, w21, z1b);
        }
        *reinterpret_cast<float4*>(reinterpret_cast<float*>(g_q) + 2 * j) =
            make_float4(z0a * dv.x, z1a * dv.x, z0b * dv.y, z1b * dv.y);
    } else if (j < n) {
        float dv = g_dinv[j];
        float s1 = dv * (g_a1[j] + g_p[j]);
        float z0 = 0.0f, z1 = 0.0f;
        #pragma unroll
        for (int k = 0; k < 16; k++) {
            float h = fmaxf(fmaf(s1, sW1[k], sb1[k]), 0.0f);
            z0 = fmaf(h, sW2[2 * k + 0], z0);
            z1 = fmaf(h, sW2[2 * k + 1], z1);
        }
        g_q[j] = make_float2(z0 * dv, z1 * dv);
    }
}

// ---------------- layer-2 vector scatter: a2[dst] += q[src] (float2 RED) ----
__global__ void __launch_bounds__(256) k_scatter2(const int* __restrict__ src,
                                                  const int* __restrict__ dst, int ne) {
    int i = blockIdx.x * blockDim.x + threadIdx.x;
    int e = i * 4;
    if (e + 4 <= ne) {
        int4 s = *reinterpret_cast<const int4*>(src + e);
        int4 d = *reinterpret_cast<const int4*>(dst + e);
        float2 q0 = __ldcg(&g_q[s.x]);
        float2 q1 = __ldcg(&g_q[s.y]);
        float2 q2 = __ldcg(&g_q[s.z]);
        float2 q3 = __ldcg(&g_q[s.w]);
        atomicAdd(&g_a2[d.x], q0);
        atomicAdd(&g_a2[d.y], q1);
        atomicAdd(&g_a2[d.z], q2);
        atomicAdd(&g_a2[d.w], q3);
    } else {
        for (; e < ne; e++) {
            atomicAdd(&g_a2[dst[e]], __ldcg(&g_q[src[e]]));
        }
    }
}

// ---------------- finalize: out = log_softmax(dinv*(a2+q) + b2), 2 nodes/thread ----
__global__ void __launch_bounds__(256) k_final(const float* __restrict__ b2,
                                               float* __restrict__ out, int n) {
    int i = blockIdx.x * blockDim.x + threadIdx.x;
    int j = i * 2;
    float bb0 = __ldg(&b2[0]), bb1 = __ldg(&b2[1]);
    if (j + 2 <= n) {
        float2 dv2 = *reinterpret_cast<const float2*>(g_dinv + j);
        float4 q = *reinterpret_cast<const float4*>(reinterpret_cast<const float*>(g_q) + 2 * j);
        float4 a = *reinterpret_cast<const float4*>(reinterpret_cast<const float*>(g_a2) + 2 * j);
        float v0 = fmaf(dv2.x, a.x + q.x, bb0);
        float v1 = fmaf(dv2.x, a.y + q.y, bb1);
        float m0 = fmaxf(v0, v1);
        float l0 = m0 + logf(expf(v0 - m0) + expf(v1 - m0));
        float v2 = fmaf(dv2.y, a.z + q.z, bb0);
        float v3 = fmaf(dv2.y, a.w + q.w, bb1);
        float m1 = fmaxf(v2, v3);
        float l1 = m1 + logf(expf(v2 - m1) + expf(v3 - m1));
        *reinterpret_cast<float4*>(out + 2 * j) =
            make_float4(v0 - l0, v1 - l0, v2 - l1, v3 - l1);
    } else if (j < n) {
        float dv = g_dinv[j];
        float2 q = g_q[j];
        float2 a = g_a2[j];
        float v0 = fmaf(dv, a.x + q.x, bb0);
        float v1 = fmaf(dv, a.y + q.y, bb1);
        float m = fmaxf(v0, v1);
        float lse = m + logf(expf(v0 - m) + expf(v1 - m));
        out[2 * j + 0] = v0 - lse;
        out[2 * j + 1] = v1 - lse;
    }
}

extern "C" void kernel_launch(void* const* d_in, const int* in_sizes, int n_in,
                              void* d_out, int out_size) {
    const float* x  = (const float*)d_in[0];
    const int*   ei = (const int*)d_in[1];
    const float* W1 = (const float*)d_in[2];
    const float* b1 = (const float*)d_in[3];
    const float* W2 = (const float*)d_in[4];
    const float* b2 = (const float*)d_in[5];
    float* out = (float*)d_out;

    int n  = in_sizes[0];          // N nodes (x is [N,1])
    int ne = in_sizes[1] / 2;      // edge_index is [2, E]
    const int* src = ei;
    const int* dst = ei + ne;

    // zero scratch via memset nodes (graph-capturable, no kernel launch)
    void* p_deg = nullptr; void* p_a1 = nullptr; void* p_a2 = nullptr;
    cudaGetSymbolAddress(&p_deg, g_deg);
    cudaGetSymbolAddress(&p_a1, g_a1);
    cudaGetSymbolAddress(&p_a2, g_a2);
    cudaMemsetAsync(p_deg, 0, (size_t)n * sizeof(float));
    cudaMemsetAsync(p_a1, 0, (size_t)n * sizeof(float));
    cudaMemsetAsync(p_a2, 0, (size_t)n * sizeof(float2));

    const int T = 256;
    int gridN4  = ((n + 3) / 4 + T - 1) / T;
    int gridN2t = ((n + 1) / 2 + T - 1) / T;
    int gridE4  = ((ne + 3) / 4 + T - 1) / T;

    k_count<<<gridE4, T>>>(dst, ne);
    k_prep<<<gridN4, T>>>(x, n);
    k_scatter1<<<gridE4, T>>>(src, dst, ne);
    k_node<<<gridN2t, T>>>(W1, b1, W2, n);
    k_scatter2<<<gridE4, T>>>(src, dst, ne);
    k_final<<<gridN2t, T>>>(b2, out, n);
}